// round 9
// baseline (speedup 1.0000x reference)
#include <cuda_runtime.h>
#include <cuda_bf16.h>
#include <cstdint>

#define TT 4
#define BB 4
#define NN 1024
#define DD 512
#define HH 8
#define HDIM 64
#define MM (TT*BB*NN)   // 16384 total rows
#define EPSV 1e-6f

// ---------------- scratch (device globals: allocation-free rule) ----------------
__device__ __nv_bfloat16 g_qkvhi[3 * MM * DD];   // [q; k; v] hi
__device__ __nv_bfloat16 g_qkvlo[3 * MM * DD];   // [q; k; v] lo
__device__ __nv_bfloat16 g_xhi[MM * DD];
__device__ __nv_bfloat16 g_xlo[MM * DD];
__device__ __nv_bfloat16 g_ctxhi[MM * DD];
__device__ __nv_bfloat16 g_ctxlo[MM * DD];
__device__ __nv_bfloat16 g_whi[4 * DD * DD];     // [wq; wk; wv; wo] hi
__device__ __nv_bfloat16 g_wlo[4 * DD * DD];
__device__ float g_bias[3 * DD];                 // [bq; bk; bv]

// ---------------- PTX helpers (base ISA: ldmatrix + mma.sync + cp.async) ------
__device__ __forceinline__ uint32_t smem_u32(const void* p) {
    uint32_t a;
    asm("{ .reg .u64 t; cvta.to.shared.u64 t, %1; cvt.u32.u64 %0, t; }" : "=r"(a) : "l"(p));
    return a;
}
__device__ __forceinline__ void ldsm_x4(uint32_t& r0, uint32_t& r1, uint32_t& r2, uint32_t& r3,
                                        uint32_t addr) {
    asm volatile("ldmatrix.sync.aligned.m8n8.x4.shared.b16 {%0,%1,%2,%3}, [%4];"
                 : "=r"(r0), "=r"(r1), "=r"(r2), "=r"(r3) : "r"(addr));
}
__device__ __forceinline__ void ldsm_x4_t(uint32_t& r0, uint32_t& r1, uint32_t& r2, uint32_t& r3,
                                          uint32_t addr) {
    asm volatile("ldmatrix.sync.aligned.m8n8.x4.trans.shared.b16 {%0,%1,%2,%3}, [%4];"
                 : "=r"(r0), "=r"(r1), "=r"(r2), "=r"(r3) : "r"(addr));
}
__device__ __forceinline__ void mma_bf16(float& c0, float& c1, float& c2, float& c3,
                                         uint32_t a0, uint32_t a1, uint32_t a2, uint32_t a3,
                                         uint32_t b0, uint32_t b1) {
    asm volatile(
        "mma.sync.aligned.m16n8k16.row.col.f32.bf16.bf16.f32 "
        "{%0,%1,%2,%3}, {%4,%5,%6,%7}, {%8,%9}, {%0,%1,%2,%3};"
        : "+f"(c0), "+f"(c1), "+f"(c2), "+f"(c3)
        : "r"(a0), "r"(a1), "r"(a2), "r"(a3), "r"(b0), "r"(b1));
}
__device__ __forceinline__ void mma4(float* c, const uint32_t* a, uint32_t b0, uint32_t b1) {
    mma_bf16(c[0], c[1], c[2], c[3], a[0], a[1], a[2], a[3], b0, b1);
}
__device__ __forceinline__ void cp16(uint32_t saddr, const void* g) {
    asm volatile("cp.async.cg.shared.global [%0], [%1], 16;" :: "r"(saddr), "l"(g) : "memory");
}
__device__ __forceinline__ void cp_commit() {
    asm volatile("cp.async.commit_group;" ::: "memory");
}
__device__ __forceinline__ void cp_wait0() {
    asm volatile("cp.async.wait_group 0;" ::: "memory");
}
__device__ __forceinline__ void cp_wait1() {
    asm volatile("cp.async.wait_group 1;" ::: "memory");
}
__device__ __forceinline__ void cp_wait2() {
    asm volatile("cp.async.wait_group 2;" ::: "memory");
}
__device__ __forceinline__ void pack_split(float x, float y, uint32_t& hi, uint32_t& lo) {
    __nv_bfloat16 hx = __float2bfloat16(x), hy = __float2bfloat16(y);
    __nv_bfloat162 ph; ph.x = hx; ph.y = hy;
    __nv_bfloat162 pl;
    pl.x = __float2bfloat16(x - __bfloat162float(hx));
    pl.y = __float2bfloat16(y - __bfloat162float(hy));
    hi = *(uint32_t*)&ph;
    lo = *(uint32_t*)&pl;
}

// ---------------- fp32 -> bf16 hi/lo splits ----------------
__global__ __launch_bounds__(256) void convert_split_kernel(
    const float4* __restrict__ src,
    __nv_bfloat162* __restrict__ hi, __nv_bfloat162* __restrict__ lo, int n4)
{
    int i = blockIdx.x * blockDim.x + threadIdx.x;
    if (i >= n4) return;
    float4 v = src[i];
    uint32_t h0, l0, h1, l1;
    pack_split(v.x, v.y, h0, l0);
    pack_split(v.z, v.w, h1, l1);
    hi[2 * i]     = *(__nv_bfloat162*)&h0;
    hi[2 * i + 1] = *(__nv_bfloat162*)&h1;
    lo[2 * i]     = *(__nv_bfloat162*)&l0;
    lo[2 * i + 1] = *(__nv_bfloat162*)&l1;
}

__global__ __launch_bounds__(256) void convert_w_kernel(
    const float4* __restrict__ w0, const float4* __restrict__ w1,
    const float4* __restrict__ w2, const float4* __restrict__ w3,
    __nv_bfloat162* __restrict__ hi, __nv_bfloat162* __restrict__ lo)
{
    const int n4seg = DD * DD / 4;
    int i = blockIdx.x * blockDim.x + threadIdx.x;
    if (i >= 4 * n4seg) return;
    const int seg = i / n4seg;
    const int j   = i - seg * n4seg;
    const float4* src = (seg == 0) ? w0 : (seg == 1) ? w1 : (seg == 2) ? w2 : w3;
    float4 v = src[j];
    uint32_t h0, l0, h1, l1;
    pack_split(v.x, v.y, h0, l0);
    pack_split(v.z, v.w, h1, l1);
    hi[2 * i]     = *(__nv_bfloat162*)&h0;
    hi[2 * i + 1] = *(__nv_bfloat162*)&h1;
    lo[2 * i]     = *(__nv_bfloat162*)&l0;
    lo[2 * i + 1] = *(__nv_bfloat162*)&l1;
}

// ---------------------------------------------------------------------------
// mma.sync GEMM, 2-stage cp.async pipeline.
// CTA tile 64(M) x 128(N), 8 warps (2m x 4n), warp tile 32x32, BK=32.
// 3 CTAs/SM target: acc 32 regs, smem 61440 B.
// ---------------------------------------------------------------------------
#define TSTRIDE 80
#define A_TILE_B (64 * TSTRIDE)    // 5120
#define B_TILE_B (128 * TSTRIDE)   // 10240
#define OAH 0
#define OAL A_TILE_B
#define OBH (2 * A_TILE_B)
#define OBL (2 * A_TILE_B + B_TILE_B)
#define GSTAGE  (2 * A_TILE_B + 2 * B_TILE_B)   // 30720
#define GEMM_SMEM (2 * GSTAGE)                  // 61440

template<int MODE>
__global__ __launch_bounds__(256, 3) void gemm_mma_kernel(
    const __nv_bfloat16* __restrict__ Ahi, const __nv_bfloat16* __restrict__ Alo,
    const __nv_bfloat16* __restrict__ Bhi, const __nv_bfloat16* __restrict__ Blo,
    const float* __restrict__ bias, float* __restrict__ C,
    __nv_bfloat16* __restrict__ Chi, __nv_bfloat16* __restrict__ Clo)
{
    extern __shared__ __align__(128) char gsm[];
    const uint32_t sb = smem_u32(gsm);

    const int tid = threadIdx.x;
    const int wid = tid >> 5;
    const int lane = tid & 31;
    const int warp_m = wid & 1;        // 0..1 -> 32-row slice
    const int warp_n = wid >> 1;       // 0..3 -> 32-col slice
    const int m0 = blockIdx.y * 64;
    const int n0 = blockIdx.x * 128;   // global column (may exceed 512 in fused mode)

    const uint4* gAh = (const uint4*)Ahi;
    const uint4* gAl = (const uint4*)Alo;
    const uint4* gBh = (const uint4*)Bhi;
    const uint4* gBl = (const uint4*)Blo;

    auto issue_stage = [&](int c, int buf) {
        const int kq = c * 4;
        const uint32_t st = sb + buf * GSTAGE;
        // A: 64 rows x 4 uint4 = 256 -> 1 per thread
        {
            const int row = tid >> 2;
            const int q   = tid & 3;
            const uint32_t so = (uint32_t)(row * TSTRIDE + q * 16);
            const size_t ga = (size_t)(m0 + row) * 64 + kq + q;
            cp16(st + OAH + so, &gAh[ga]);
            cp16(st + OAL + so, &gAl[ga]);
        }
        // B: 128 rows x 4 uint4 = 512 -> 2 per thread
        #pragma unroll
        for (int i = 0; i < 2; i++) {
            const int e   = i * 256 + tid;
            const int row = e >> 2;
            const int q   = e & 3;
            const uint32_t so = (uint32_t)(row * TSTRIDE + q * 16);
            const size_t gb = (size_t)(n0 + row) * 64 + kq + q;
            cp16(st + OBH + so, &gBh[gb]);
            cp16(st + OBL + so, &gBl[gb]);
        }
        cp_commit();
    };

    float acc[2][4][4];
    #pragma unroll
    for (int i = 0; i < 2; i++)
        #pragma unroll
        for (int j = 0; j < 4; j++)
            #pragma unroll
            for (int r = 0; r < 4; r++)
                acc[i][j][r] = 0.f;

    const uint32_t a_lrow = (uint32_t)(lane & 15);
    const uint32_t a_lcol = (uint32_t)((lane >> 4) * 16);
    const uint32_t b_lrow = (uint32_t)(((lane >> 4) & 1) * 8 + (lane & 7));
    const uint32_t b_lcol = (uint32_t)(((lane >> 3) & 1) * 16);

    issue_stage(0, 0);

    for (int c = 0; c < 16; c++) {
        cp_wait0();
        __syncthreads();                       // visibility of stage c + WAR guard
        if (c + 1 < 16) issue_stage(c + 1, (c + 1) & 1);

        const uint32_t st = sb + (c & 1) * GSTAGE;

        #pragma unroll
        for (int ks = 0; ks < 2; ks++) {
            const uint32_t kb = (uint32_t)(ks * 32);
            uint32_t bh[4][2], bl[4][2];
            #pragma unroll
            for (int p = 0; p < 2; p++) {
                const uint32_t boff =
                    (uint32_t)(warp_n * 32 + p * 16 + b_lrow) * TSTRIDE + b_lcol + kb;
                ldsm_x4(bh[2*p][0], bh[2*p][1], bh[2*p+1][0], bh[2*p+1][1], st + OBH + boff);
                ldsm_x4(bl[2*p][0], bl[2*p][1], bl[2*p+1][0], bl[2*p+1][1], st + OBL + boff);
            }
            #pragma unroll
            for (int mt = 0; mt < 2; mt++) {
                const uint32_t aoff =
                    (uint32_t)(warp_m * 32 + mt * 16 + a_lrow) * TSTRIDE + a_lcol + kb;
                uint32_t ah0, ah1, ah2, ah3, al0, al1, al2, al3;
                ldsm_x4(ah0, ah1, ah2, ah3, st + OAH + aoff);
                ldsm_x4(al0, al1, al2, al3, st + OAL + aoff);
                #pragma unroll
                for (int nt = 0; nt < 4; nt++) {
                    mma_bf16(acc[mt][nt][0], acc[mt][nt][1], acc[mt][nt][2], acc[mt][nt][3],
                             ah0, ah1, ah2, ah3, bh[nt][0], bh[nt][1]);
                    mma_bf16(acc[mt][nt][0], acc[mt][nt][1], acc[mt][nt][2], acc[mt][nt][3],
                             ah0, ah1, ah2, ah3, bl[nt][0], bl[nt][1]);
                    mma_bf16(acc[mt][nt][0], acc[mt][nt][1], acc[mt][nt][2], acc[mt][nt][3],
                             al0, al1, al2, al3, bh[nt][0], bh[nt][1]);
                }
            }
        }
    }

    // epilogue (segment-relocated for fused QKV when MODE==1)
    const int seg  = n0 >> 9;
    const int nloc = n0 & 511;
    const size_t segoff = (size_t)seg * MM * DD;
    const int rbase = m0 + warp_m * 32 + (lane >> 2);
    const int cbase = nloc + warp_n * 32 + (lane & 3) * 2;
    #pragma unroll
    for (int mt = 0; mt < 2; mt++) {
        #pragma unroll
        for (int nt = 0; nt < 4; nt++) {
            const int col = cbase + nt * 8;
            const float b0 = bias[(n0 & ~511) + col];
            const float b1 = bias[(n0 & ~511) + col + 1];
            const int r0 = rbase + mt * 16;
            const float o00 = acc[mt][nt][0] + b0, o01 = acc[mt][nt][1] + b1;
            const float o10 = acc[mt][nt][2] + b0, o11 = acc[mt][nt][3] + b1;
            if (MODE == 0) {
                *(float2*)&C[(size_t)r0 * DD + col]       = make_float2(o00, o01);
                *(float2*)&C[(size_t)(r0 + 8) * DD + col] = make_float2(o10, o11);
            } else {
                uint32_t h0, l0, h1, l1;
                pack_split(o00, o01, h0, l0);
                pack_split(o10, o11, h1, l1);
                *(uint32_t*)&Chi[segoff + (size_t)r0 * DD + col]       = h0;
                *(uint32_t*)&Clo[segoff + (size_t)r0 * DD + col]       = l0;
                *(uint32_t*)&Chi[segoff + (size_t)(r0 + 8) * DD + col] = h1;
                *(uint32_t*)&Clo[segoff + (size_t)(r0 + 8) * DD + col] = l1;
            }
        }
    }
}

// ---------------------------------------------------------------------------
// Tensor-core fused relu-normalized attention, 3-stage cp.async ring.
// ---------------------------------------------------------------------------
#define ASTRIDE 144
#define STGSZ 36864            // K hi/lo + V hi/lo per 64-row tile
#define AK_H  0
#define AK_L  9216
#define AV_H  18432
#define AV_L  27648
#define ATTN_SMEM (3 * STGSZ)  // 110592 -> 2 CTAs/SM

__global__ __launch_bounds__(256, 2) void attn_mma_kernel(
    const __nv_bfloat16* __restrict__ qkvhi, const __nv_bfloat16* __restrict__ qkvlo,
    __nv_bfloat16* __restrict__ ctxhi, __nv_bfloat16* __restrict__ ctxlo)
{
    extern __shared__ __align__(128) char smem_[];
    const uint32_t sb = smem_u32(smem_);

    const int tid = threadIdx.x;
    const int wid = tid >> 5;
    const int lane = tid & 31;
    const int qt = blockIdx.x;      // 0..7
    const int h  = blockIdx.y;      // 0..7
    const int tb = blockIdx.z;      // 0..15
    const size_t rowbase = (size_t)tb * NN;
    const int col0 = h * HDIM;
    const int q0 = qt * 128;
    const int cq8 = col0 >> 3;

    const uint4* gqh = (const uint4*)qkvhi;
    const uint4* gql = (const uint4*)qkvlo;
    const uint4* gkh = (const uint4*)(qkvhi + (size_t)MM * DD);
    const uint4* gkl = (const uint4*)(qkvlo + (size_t)MM * DD);
    const uint4* gvh = (const uint4*)(qkvhi + (size_t)2 * MM * DD);
    const uint4* gvl = (const uint4*)(qkvlo + (size_t)2 * MM * DD);

    const int lr = tid >> 3;        // 0..31
    const int lch = tid & 7;
    const uint32_t lso = (uint32_t)(lr * ASTRIDE + lch * 16);

    auto issue_stage = [&](int kt, int buf) {
        const uint32_t st = sb + buf * STGSZ;
        #pragma unroll
        for (int half = 0; half < 2; half++) {
            const int r = half * 32 + lr;
            const uint32_t so = lso + (uint32_t)(half * 32 * ASTRIDE);
            const size_t g = (rowbase + kt * 64 + r) * 64 + cq8 + lch;
            cp16(st + AK_H + so, &gkh[g]);
            cp16(st + AK_L + so, &gkl[g]);
            cp16(st + AV_H + so, &gvh[g]);
            cp16(st + AV_L + so, &gvl[g]);
        }
        cp_commit();
    };

    // ---- Q into buffer 2 (group 0), then K/V stages 0,1 (groups 1,2) ----
    {
        const uint32_t qb = sb + 2 * STGSZ;
        #pragma unroll
        for (int it = 0; it < 4; it++) {
            const int idx = it * 256 + tid;     // 0..1023
            const int r  = idx >> 3;
            const int ch = idx & 7;
            const size_t g = (rowbase + q0 + r) * 64 + cq8 + ch;
            const uint32_t so = (uint32_t)(r * ASTRIDE + ch * 16);
            cp16(qb + so,         &gqh[g]);
            cp16(qb + 18432 + so, &gql[g]);
        }
        cp_commit();
    }
    issue_stage(0, 0);
    issue_stage(1, 1);
    cp_wait2();                 // Q complete (stages 0,1 may still be in flight)
    __syncthreads();

    const uint32_t a_lrow = (uint32_t)(lane & 15);
    const uint32_t a_lcol = (uint32_t)((lane >> 4) * 16);
    const uint32_t b_lrow = (uint32_t)(((lane >> 4) & 1) * 8 + (lane & 7));
    const uint32_t b_lcol = (uint32_t)(((lane >> 3) & 1) * 16);
    const uint32_t v_lrow = (uint32_t)(lane & 15);
    const uint32_t v_lcol = (uint32_t)((lane >> 4) * 16);

    // ---- Q fragments from buffer 2 (it joins the ring at kt=0's issue(2)) ----
    uint32_t qh[4][4], ql[4][4];
    #pragma unroll
    for (int ks = 0; ks < 4; ks++) {
        const uint32_t aoff = (uint32_t)(wid * 16 + a_lrow) * ASTRIDE + a_lcol + ks * 32;
        ldsm_x4(qh[ks][0], qh[ks][1], qh[ks][2], qh[ks][3], sb + 2 * STGSZ + aoff);
        ldsm_x4(ql[ks][0], ql[ks][1], ql[ks][2], ql[ks][3], sb + 2 * STGSZ + 18432 + aoff);
    }

    float acc[8][4];
    #pragma unroll
    for (int i = 0; i < 8; i++)
        #pragma unroll
        for (int j = 0; j < 4; j++)
            acc[i][j] = 0.f;
    float dsum0 = 0.f, dsum1 = 0.f;

    for (int kt = 0; kt < 16; kt++) {
        if (kt < 15) cp_wait1(); else cp_wait0();
        __syncthreads();        // stage kt visible; Q-frag reads / old readers done
        if (kt + 2 < 16) issue_stage(kt + 2, (kt + 2) % 3);

        const uint32_t st = sb + (kt % 3) * STGSZ;

        // ---- phase 1: S = Q K^T (3-split) ----
        float s[8][4];
        #pragma unroll
        for (int i = 0; i < 8; i++)
            #pragma unroll
            for (int j = 0; j < 4; j++)
                s[i][j] = 0.f;

        #pragma unroll
        for (int ks = 0; ks < 4; ks++) {
            #pragma unroll
            for (int p = 0; p < 4; p++) {
                const uint32_t boff = (uint32_t)(p * 16 + b_lrow) * ASTRIDE + b_lcol + ks * 32;
                uint32_t kh0, kh1, kh2, kh3, kl0, kl1, kl2, kl3;
                ldsm_x4(kh0, kh1, kh2, kh3, st + AK_H + boff);
                ldsm_x4(kl0, kl1, kl2, kl3, st + AK_L + boff);
                mma4(s[2*p],     qh[ks], kh0, kh1);
                mma4(s[2*p],     qh[ks], kl0, kl1);
                mma4(s[2*p],     ql[ks], kh0, kh1);
                mma4(s[2*p + 1], qh[ks], kh2, kh3);
                mma4(s[2*p + 1], qh[ks], kl2, kl3);
                mma4(s[2*p + 1], ql[ks], kh2, kh3);
            }
        }

        // ---- relu/scale, denominator, repack as A fragments ----
        #pragma unroll
        for (int nt = 0; nt < 8; nt++) {
            #pragma unroll
            for (int e = 0; e < 4; e++)
                s[nt][e] = fmaxf(s[nt][e] * 0.125f, 0.f);
            dsum0 += s[nt][0] + s[nt][1];
            dsum1 += s[nt][2] + s[nt][3];
        }
        uint32_t ahi[4][4], alo[4][4];
        #pragma unroll
        for (int g = 0; g < 4; g++) {
            pack_split(s[2*g][0],     s[2*g][1],     ahi[g][0], alo[g][0]);
            pack_split(s[2*g][2],     s[2*g][3],     ahi[g][1], alo[g][1]);
            pack_split(s[2*g + 1][0], s[2*g + 1][1], ahi[g][2], alo[g][2]);
            pack_split(s[2*g + 1][2], s[2*g + 1][3], ahi[g][3], alo[g][3]);
        }

        // ---- phase 2: ctx += S V (3-split, V natural + ldmatrix.trans) ----
        #pragma unroll
        for (int g = 0; g < 4; g++) {
            const uint32_t grow = (uint32_t)(g * 16 + v_lrow) * ASTRIDE + v_lcol;
            #pragma unroll
            for (int p = 0; p < 4; p++) {
                const uint32_t vaddr = grow + p * 32;
                uint32_t vh0, vh1, vh2, vh3, vl0, vl1, vl2, vl3;
                ldsm_x4_t(vh0, vh1, vh2, vh3, st + AV_H + vaddr);
                ldsm_x4_t(vl0, vl1, vl2, vl3, st + AV_L + vaddr);
                mma4(acc[2*p],     ahi[g], vh0, vh1);
                mma4(acc[2*p],     ahi[g], vl0, vl1);
                mma4(acc[2*p],     alo[g], vh0, vh1);
                mma4(acc[2*p + 1], ahi[g], vh2, vh3);
                mma4(acc[2*p + 1], ahi[g], vl2, vl3);
                mma4(acc[2*p + 1], alo[g], vh2, vh3);
            }
        }
    }

    // ---- denominator reduce across the quad (cols), normalize, write ----
    dsum0 += __shfl_xor_sync(0xffffffffu, dsum0, 1);
    dsum0 += __shfl_xor_sync(0xffffffffu, dsum0, 2);
    dsum1 += __shfl_xor_sync(0xffffffffu, dsum1, 1);
    dsum1 += __shfl_xor_sync(0xffffffffu, dsum1, 2);
    const float inv0 = 1.f / (dsum0 + EPSV);
    const float inv1 = 1.f / (dsum1 + EPSV);

    const size_t r0 = rowbase + q0 + wid * 16 + (lane >> 2);
    const int ccol = (lane & 3) * 2;
    #pragma unroll
    for (int nt = 0; nt < 8; nt++) {
        const int col = col0 + nt * 8 + ccol;
        uint32_t h0, l0, h1, l1;
        pack_split(acc[nt][0] * inv0, acc[nt][1] * inv0, h0, l0);
        pack_split(acc[nt][2] * inv1, acc[nt][3] * inv1, h1, l1);
        *(uint32_t*)&ctxhi[r0 * DD + col]       = h0;
        *(uint32_t*)&ctxlo[r0 * DD + col]       = l0;
        *(uint32_t*)&ctxhi[(r0 + 8) * DD + col] = h1;
        *(uint32_t*)&ctxlo[(r0 + 8) * DD + col] = l1;
    }
}

// ---------------------------------------------------------------------------
extern "C" void kernel_launch(void* const* d_in, const int* in_sizes, int n_in,
                              void* d_out, int out_size)
{
    (void)in_sizes; (void)n_in; (void)out_size;
    const float* x  = (const float*)d_in[0];
    const float* wq = (const float*)d_in[1];
    const float* bq = (const float*)d_in[2];
    const float* wk = (const float*)d_in[3];
    const float* bk = (const float*)d_in[4];
    const float* wv = (const float*)d_in[5];
    const float* bv = (const float*)d_in[6];
    const float* wo = (const float*)d_in[7];
    const float* bo = (const float*)d_in[8];
    float* out = (float*)d_out;

    void *pqkh, *pqkl, *pxh, *pxl, *pch, *pcl, *pwh, *pwl, *pbias;
    cudaGetSymbolAddress(&pqkh, g_qkvhi);
    cudaGetSymbolAddress(&pqkl, g_qkvlo);
    cudaGetSymbolAddress(&pxh, g_xhi);
    cudaGetSymbolAddress(&pxl, g_xlo);
    cudaGetSymbolAddress(&pch, g_ctxhi);
    cudaGetSymbolAddress(&pcl, g_ctxlo);
    cudaGetSymbolAddress(&pwh, g_whi);
    cudaGetSymbolAddress(&pwl, g_wlo);
    cudaGetSymbolAddress(&pbias, g_bias);
    __nv_bfloat16* qkvhi = (__nv_bfloat16*)pqkh;
    __nv_bfloat16* qkvlo = (__nv_bfloat16*)pqkl;
    __nv_bfloat16* xhi = (__nv_bfloat16*)pxh;
    __nv_bfloat16* xlo = (__nv_bfloat16*)pxl;
    __nv_bfloat16* chi = (__nv_bfloat16*)pch;
    __nv_bfloat16* clo = (__nv_bfloat16*)pcl;
    __nv_bfloat16* whi = (__nv_bfloat16*)pwh;
    __nv_bfloat16* wlo = (__nv_bfloat16*)pwl;
    float* biasqkv = (float*)pbias;

    cudaFuncSetAttribute(attn_mma_kernel,    cudaFuncAttributeMaxDynamicSharedMemorySize, ATTN_SMEM);
    cudaFuncSetAttribute(gemm_mma_kernel<0>, cudaFuncAttributeMaxDynamicSharedMemorySize, GEMM_SMEM);
    cudaFuncSetAttribute(gemm_mma_kernel<1>, cudaFuncAttributeMaxDynamicSharedMemorySize, GEMM_SMEM);

    // bias concat [bq; bk; bv]
    cudaMemcpyAsync(biasqkv,            bq, DD * sizeof(float), cudaMemcpyDeviceToDevice);
    cudaMemcpyAsync(biasqkv + DD,       bk, DD * sizeof(float), cudaMemcpyDeviceToDevice);
    cudaMemcpyAsync(biasqkv + 2 * DD,   bv, DD * sizeof(float), cudaMemcpyDeviceToDevice);

    // fp32 -> bf16 hi/lo splits
    {
        const int n4x = MM * DD / 4;
        convert_split_kernel<<<(n4x + 255) / 256, 256>>>(
            (const float4*)x, (__nv_bfloat162*)xhi, (__nv_bfloat162*)xlo, n4x);
        const int n4wall = 4 * DD * DD / 4;
        convert_w_kernel<<<(n4wall + 255) / 256, 256>>>(
            (const float4*)wq, (const float4*)wk, (const float4*)wv, (const float4*)wo,
            (__nv_bfloat162*)whi, (__nv_bfloat162*)wlo);
    }

    // fused QKV projection: N = 1536, M-tiles of 64
    gemm_mma_kernel<1><<<dim3(12, MM / 64), 256, GEMM_SMEM>>>(
        xhi, xlo, whi, wlo, biasqkv, nullptr, qkvhi, qkvlo);

    attn_mma_kernel<<<dim3(8, HH, TT * BB), 256, ATTN_SMEM>>>(qkvhi, qkvlo, chi, clo);

    // output projection
    gemm_mma_kernel<0><<<dim3(4, MM / 64), 256, GEMM_SMEM>>>(
        chi, clo, whi + (size_t)3 * DD * DD, wlo + (size_t)3 * DD * DD, bo, out, nullptr, nullptr);
}

// round 11
// speedup vs baseline: 2.4780x; 2.4780x over previous
#include <cuda_runtime.h>
#include <cuda_fp16.h>
#include <cstdint>

#define TT 4
#define BB 4
#define NN 1024
#define DD 512
#define HH 8
#define HDIM 64
#define MM (TT*BB*NN)   // 16384 total rows
#define EPSV 1e-6f

// ---------------- scratch (device globals: allocation-free rule) ----------------
__device__ __half g_qkv[3 * MM * DD];     // [q; k; v]
__device__ __half g_x[MM * DD];
__device__ __half g_ctx[MM * DD];
__device__ __half g_w[4 * DD * DD];       // [wq; wk; wv; wo]
__device__ float g_bias[3 * DD];          // [bq; bk; bv]

// ---------------- PTX helpers (base ISA: ldmatrix + mma.sync + cp.async) ------
__device__ __forceinline__ uint32_t smem_u32(const void* p) {
    uint32_t a;
    asm("{ .reg .u64 t; cvta.to.shared.u64 t, %1; cvt.u32.u64 %0, t; }" : "=r"(a) : "l"(p));
    return a;
}
__device__ __forceinline__ void ldsm_x4(uint32_t& r0, uint32_t& r1, uint32_t& r2, uint32_t& r3,
                                        uint32_t addr) {
    asm volatile("ldmatrix.sync.aligned.m8n8.x4.shared.b16 {%0,%1,%2,%3}, [%4];"
                 : "=r"(r0), "=r"(r1), "=r"(r2), "=r"(r3) : "r"(addr));
}
__device__ __forceinline__ void ldsm_x4_t(uint32_t& r0, uint32_t& r1, uint32_t& r2, uint32_t& r3,
                                          uint32_t addr) {
    asm volatile("ldmatrix.sync.aligned.m8n8.x4.trans.shared.b16 {%0,%1,%2,%3}, [%4];"
                 : "=r"(r0), "=r"(r1), "=r"(r2), "=r"(r3) : "r"(addr));
}
__device__ __forceinline__ void mma_f16(float& c0, float& c1, float& c2, float& c3,
                                        uint32_t a0, uint32_t a1, uint32_t a2, uint32_t a3,
                                        uint32_t b0, uint32_t b1) {
    asm volatile(
        "mma.sync.aligned.m16n8k16.row.col.f32.f16.f16.f32 "
        "{%0,%1,%2,%3}, {%4,%5,%6,%7}, {%8,%9}, {%0,%1,%2,%3};"
        : "+f"(c0), "+f"(c1), "+f"(c2), "+f"(c3)
        : "r"(a0), "r"(a1), "r"(a2), "r"(a3), "r"(b0), "r"(b1));
}
__device__ __forceinline__ void mma4(float* c, const uint32_t* a, uint32_t b0, uint32_t b1) {
    mma_f16(c[0], c[1], c[2], c[3], a[0], a[1], a[2], a[3], b0, b1);
}
__device__ __forceinline__ void cp16(uint32_t saddr, const void* g) {
    asm volatile("cp.async.cg.shared.global [%0], [%1], 16;" :: "r"(saddr), "l"(g) : "memory");
}
__device__ __forceinline__ void cp_commit() {
    asm volatile("cp.async.commit_group;" ::: "memory");
}
__device__ __forceinline__ void cp_wait0() {
    asm volatile("cp.async.wait_group 0;" ::: "memory");
}
__device__ __forceinline__ void cp_wait1() {
    asm volatile("cp.async.wait_group 1;" ::: "memory");
}
__device__ __forceinline__ void cp_wait2() {
    asm volatile("cp.async.wait_group 2;" ::: "memory");
}
__device__ __forceinline__ uint32_t pack_h2(float x, float y) {
    __half2 h = __floats2half2_rn(x, y);
    return *(uint32_t*)&h;
}

// ---------------- fp32 -> fp16 convert ----------------
__global__ __launch_bounds__(256) void convert_h_kernel(
    const float4* __restrict__ src, uint32_t* __restrict__ dst, int n4)
{
    int i = blockIdx.x * blockDim.x + threadIdx.x;
    if (i >= n4) return;
    float4 v = src[i];
    dst[2 * i]     = pack_h2(v.x, v.y);
    dst[2 * i + 1] = pack_h2(v.z, v.w);
}

// fused convert of all 4 weights
__global__ __launch_bounds__(256) void convert_w_kernel(
    const float4* __restrict__ w0, const float4* __restrict__ w1,
    const float4* __restrict__ w2, const float4* __restrict__ w3,
    uint32_t* __restrict__ dst)
{
    const int n4seg = DD * DD / 4;
    int i = blockIdx.x * blockDim.x + threadIdx.x;
    if (i >= 4 * n4seg) return;
    const int seg = i / n4seg;
    const int j   = i - seg * n4seg;
    const float4* src = (seg == 0) ? w0 : (seg == 1) ? w1 : (seg == 2) ? w2 : w3;
    float4 v = src[j];
    dst[2 * i]     = pack_h2(v.x, v.y);
    dst[2 * i + 1] = pack_h2(v.z, v.w);
}

// ---------------------------------------------------------------------------
// fp16 mma.sync GEMM, 2-stage cp.async pipeline, single barrier per chunk.
// CTA 128x128, 8 warps (2m x 4n), warp tile 64x32, BK=32.
// ---------------------------------------------------------------------------
#define TSTRIDE 80
#define TILE_B  (128 * TSTRIDE)    // 10240
#define GSTAGE  (2 * TILE_B)       // 20480 (A + B)
#define GEMM_SMEM (2 * GSTAGE)     // 40960

template<int MODE>
__global__ __launch_bounds__(256, 2) void gemm_mma_kernel(
    const __half* __restrict__ A, const __half* __restrict__ B,
    const float* __restrict__ bias, float* __restrict__ C,
    __half* __restrict__ Ch)
{
    extern __shared__ __align__(128) char gsm[];
    const uint32_t sb = smem_u32(gsm);

    const int tid = threadIdx.x;
    const int wid = tid >> 5;
    const int lane = tid & 31;
    const int warp_m = wid & 1;
    const int warp_n = wid >> 1;
    const int m0 = blockIdx.y * 128;
    const int n0 = blockIdx.x * 128;   // global column (may exceed 512 in fused mode)

    const uint4* gA = (const uint4*)A;
    const uint4* gB = (const uint4*)B;

    const int lrow = tid >> 2;
    const int lq   = tid & 3;
    const uint32_t lso = (uint32_t)(lrow * TSTRIDE + lq * 16);

    auto issue_stage = [&](int c, int buf) {
        const int kq = c * 4;
        const uint32_t st = sb + buf * GSTAGE;
        #pragma unroll
        for (int half_ = 0; half_ < 2; half_++) {
            const int row = half_ * 64 + lrow;
            const uint32_t so = lso + (uint32_t)(half_ * 64 * TSTRIDE);
            const size_t ga = (size_t)(m0 + row) * 64 + kq + lq;
            const size_t gb = (size_t)(n0 + row) * 64 + kq + lq;
            cp16(st + so,          &gA[ga]);
            cp16(st + TILE_B + so, &gB[gb]);
        }
        cp_commit();
    };

    float acc[4][4][4];
    #pragma unroll
    for (int i = 0; i < 4; i++)
        #pragma unroll
        for (int j = 0; j < 4; j++)
            #pragma unroll
            for (int r = 0; r < 4; r++)
                acc[i][j][r] = 0.f;

    const uint32_t a_lrow = (uint32_t)(lane & 15);
    const uint32_t a_lcol = (uint32_t)((lane >> 4) * 16);
    const uint32_t b_lrow = (uint32_t)(((lane >> 4) & 1) * 8 + (lane & 7));
    const uint32_t b_lcol = (uint32_t)(((lane >> 3) & 1) * 16);

    issue_stage(0, 0);

    for (int c = 0; c < 16; c++) {
        cp_wait0();
        __syncthreads();                       // visibility of stage c + WAR guard
        if (c + 1 < 16) issue_stage(c + 1, (c + 1) & 1);

        const uint32_t st = sb + (c & 1) * GSTAGE;
        const uint32_t sA = st;
        const uint32_t sB = st + TILE_B;

        #pragma unroll
        for (int ks = 0; ks < 2; ks++) {
            const uint32_t kb = (uint32_t)(ks * 32);
            uint32_t bh[4][2];
            #pragma unroll
            for (int p = 0; p < 2; p++) {
                const uint32_t boff =
                    (uint32_t)(warp_n * 32 + p * 16 + b_lrow) * TSTRIDE + b_lcol + kb;
                ldsm_x4(bh[2*p][0], bh[2*p][1], bh[2*p+1][0], bh[2*p+1][1], sB + boff);
            }
            #pragma unroll
            for (int mt = 0; mt < 4; mt++) {
                const uint32_t aoff =
                    (uint32_t)(warp_m * 64 + mt * 16 + a_lrow) * TSTRIDE + a_lcol + kb;
                uint32_t a0, a1, a2, a3;
                ldsm_x4(a0, a1, a2, a3, sA + aoff);
                #pragma unroll
                for (int nt = 0; nt < 4; nt++)
                    mma_f16(acc[mt][nt][0], acc[mt][nt][1], acc[mt][nt][2], acc[mt][nt][3],
                            a0, a1, a2, a3, bh[nt][0], bh[nt][1]);
            }
        }
    }

    // epilogue (segment-relocated for fused QKV when MODE==1)
    const int seg  = n0 >> 9;
    const int nloc = n0 & 511;
    const size_t segoff = (size_t)seg * MM * DD;
    const int rbase = m0 + warp_m * 64 + (lane >> 2);
    const int cbase = nloc + warp_n * 32 + (lane & 3) * 2;
    #pragma unroll
    for (int mt = 0; mt < 4; mt++) {
        #pragma unroll
        for (int nt = 0; nt < 4; nt++) {
            const int col = cbase + nt * 8;
            const float b0 = bias[(n0 & ~511) + col];
            const float b1 = bias[(n0 & ~511) + col + 1];
            const int r0 = rbase + mt * 16;
            const float o00 = acc[mt][nt][0] + b0, o01 = acc[mt][nt][1] + b1;
            const float o10 = acc[mt][nt][2] + b0, o11 = acc[mt][nt][3] + b1;
            if (MODE == 0) {
                *(float2*)&C[(size_t)r0 * DD + col]       = make_float2(o00, o01);
                *(float2*)&C[(size_t)(r0 + 8) * DD + col] = make_float2(o10, o11);
            } else {
                *(uint32_t*)&Ch[segoff + (size_t)r0 * DD + col]       = pack_h2(o00, o01);
                *(uint32_t*)&Ch[segoff + (size_t)(r0 + 8) * DD + col] = pack_h2(o10, o11);
            }
        }
    }
}

// ---------------------------------------------------------------------------
// fp16 tensor-core fused relu-normalized attention, 3-stage cp.async ring.
// Q stages through buffer 2 and then that buffer joins the ring.
// ---------------------------------------------------------------------------
#define ASTRIDE 144
#define STGSZ 18432            // K + V per 64-row tile (each 64*144)
#define AK_O  0
#define AV_O  9216
#define ATTN_SMEM (3 * STGSZ)  // 55296

__global__ __launch_bounds__(256, 2) void attn_mma_kernel(
    const __half* __restrict__ qkv,
    __half* __restrict__ ctx)
{
    extern __shared__ __align__(128) char smem_[];
    const uint32_t sb = smem_u32(smem_);

    const int tid = threadIdx.x;
    const int wid = tid >> 5;
    const int lane = tid & 31;
    const int qt = blockIdx.x;      // 0..7
    const int h  = blockIdx.y;      // 0..7
    const int tb = blockIdx.z;      // 0..15
    const size_t rowbase = (size_t)tb * NN;
    const int col0 = h * HDIM;
    const int q0 = qt * 128;
    const int cq8 = col0 >> 3;

    const uint4* gq = (const uint4*)qkv;
    const uint4* gk = (const uint4*)(qkv + (size_t)MM * DD);
    const uint4* gv = (const uint4*)(qkv + (size_t)2 * MM * DD);

    const int lr = tid >> 3;        // 0..31
    const int lch = tid & 7;
    const uint32_t lso = (uint32_t)(lr * ASTRIDE + lch * 16);

    auto issue_stage = [&](int kt, int buf) {
        const uint32_t st = sb + buf * STGSZ;
        #pragma unroll
        for (int half_ = 0; half_ < 2; half_++) {
            const int r = half_ * 32 + lr;
            const uint32_t so = lso + (uint32_t)(half_ * 32 * ASTRIDE);
            const size_t g = (rowbase + kt * 64 + r) * 64 + cq8 + lch;
            cp16(st + AK_O + so, &gk[g]);
            cp16(st + AV_O + so, &gv[g]);
        }
        cp_commit();
    };

    // ---- Q into buffer 2 (group 0); then K/V stages 0,1 (groups 1,2) ----
    {
        const uint32_t qb = sb + 2 * STGSZ;
        #pragma unroll
        for (int it = 0; it < 2; it++) {
            const int idx = it * 256 + tid;     // 0..511 (128 rows x 4 uint4)
            const int r  = idx >> 2;
            const int ch = idx & 3;
            // 64 half per row = 8 uint4; split across 2 cp16 slots of 2 uint4
            const size_t g = (rowbase + q0 + r) * 64 + cq8 + ch * 2;
            const uint32_t so = (uint32_t)(r * ASTRIDE + ch * 32);
            cp16(qb + so,      &gq[g]);
            cp16(qb + so + 16, &gq[g + 1]);
        }
        cp_commit();
    }
    issue_stage(0, 0);
    issue_stage(1, 1);
    cp_wait2();                 // Q complete (stages 0,1 may still be in flight)
    __syncthreads();

    const uint32_t a_lrow = (uint32_t)(lane & 15);
    const uint32_t a_lcol = (uint32_t)((lane >> 4) * 16);
    const uint32_t b_lrow = (uint32_t)(((lane >> 4) & 1) * 8 + (lane & 7));
    const uint32_t b_lcol = (uint32_t)(((lane >> 3) & 1) * 16);
    const uint32_t v_lrow = (uint32_t)(lane & 15);
    const uint32_t v_lcol = (uint32_t)((lane >> 4) * 16);

    // ---- Q fragments from buffer 2 (it joins the ring at issue(2)) ----
    uint32_t qf[4][4];
    #pragma unroll
    for (int ks = 0; ks < 4; ks++) {
        const uint32_t aoff = (uint32_t)(wid * 16 + a_lrow) * ASTRIDE + a_lcol + ks * 32;
        ldsm_x4(qf[ks][0], qf[ks][1], qf[ks][2], qf[ks][3], sb + 2 * STGSZ + aoff);
    }

    float acc[8][4];
    #pragma unroll
    for (int i = 0; i < 8; i++)
        #pragma unroll
        for (int j = 0; j < 4; j++)
            acc[i][j] = 0.f;
    float dsum0 = 0.f, dsum1 = 0.f;

    for (int kt = 0; kt < 16; kt++) {
        if (kt < 15) cp_wait1(); else cp_wait0();
        __syncthreads();        // stage kt visible; Q-frag reads / old readers done
        if (kt + 2 < 16) issue_stage(kt + 2, (kt + 2) % 3);

        const uint32_t st = sb + (kt % 3) * STGSZ;

        // ---- phase 1: S = Q K^T ----
        float s[8][4];
        #pragma unroll
        for (int i = 0; i < 8; i++)
            #pragma unroll
            for (int j = 0; j < 4; j++)
                s[i][j] = 0.f;

        #pragma unroll
        for (int ks = 0; ks < 4; ks++) {
            #pragma unroll
            for (int p = 0; p < 4; p++) {
                const uint32_t boff = (uint32_t)(p * 16 + b_lrow) * ASTRIDE + b_lcol + ks * 32;
                uint32_t k0, k1, k2, k3;
                ldsm_x4(k0, k1, k2, k3, st + AK_O + boff);
                mma4(s[2*p],     qf[ks], k0, k1);
                mma4(s[2*p + 1], qf[ks], k2, k3);
            }
        }

        // ---- relu/scale, denominator, repack as A fragments ----
        #pragma unroll
        for (int nt = 0; nt < 8; nt++) {
            #pragma unroll
            for (int e = 0; e < 4; e++)
                s[nt][e] = fmaxf(s[nt][e] * 0.125f, 0.f);
            dsum0 += s[nt][0] + s[nt][1];
            dsum1 += s[nt][2] + s[nt][3];
        }
        uint32_t af[4][4];
        #pragma unroll
        for (int g = 0; g < 4; g++) {
            af[g][0] = pack_h2(s[2*g][0],     s[2*g][1]);
            af[g][1] = pack_h2(s[2*g][2],     s[2*g][3]);
            af[g][2] = pack_h2(s[2*g + 1][0], s[2*g + 1][1]);
            af[g][3] = pack_h2(s[2*g + 1][2], s[2*g + 1][3]);
        }

        // ---- phase 2: ctx += S V (V natural + ldmatrix.trans) ----
        #pragma unroll
        for (int g = 0; g < 4; g++) {
            const uint32_t grow = (uint32_t)(g * 16 + v_lrow) * ASTRIDE + v_lcol;
            #pragma unroll
            for (int p = 0; p < 4; p++) {
                const uint32_t vaddr = grow + p * 32;
                uint32_t v0, v1, v2, v3;
                ldsm_x4_t(v0, v1, v2, v3, st + AV_O + vaddr);
                mma4(acc[2*p],     af[g], v0, v1);
                mma4(acc[2*p + 1], af[g], v2, v3);
            }
        }
    }

    // ---- denominator reduce across the quad (cols), normalize, write ----
    dsum0 += __shfl_xor_sync(0xffffffffu, dsum0, 1);
    dsum0 += __shfl_xor_sync(0xffffffffu, dsum0, 2);
    dsum1 += __shfl_xor_sync(0xffffffffu, dsum1, 1);
    dsum1 += __shfl_xor_sync(0xffffffffu, dsum1, 2);
    const float inv0 = 1.f / (dsum0 + EPSV);
    const float inv1 = 1.f / (dsum1 + EPSV);

    const size_t r0 = rowbase + q0 + wid * 16 + (lane >> 2);
    const int ccol = (lane & 3) * 2;
    #pragma unroll
    for (int nt = 0; nt < 8; nt++) {
        const int col = col0 + nt * 8 + ccol;
        *(uint32_t*)&ctx[r0 * DD + col]       = pack_h2(acc[nt][0] * inv0, acc[nt][1] * inv0);
        *(uint32_t*)&ctx[(r0 + 8) * DD + col] = pack_h2(acc[nt][2] * inv1, acc[nt][3] * inv1);
    }
}

// ---------------------------------------------------------------------------
extern "C" void kernel_launch(void* const* d_in, const int* in_sizes, int n_in,
                              void* d_out, int out_size)
{
    (void)in_sizes; (void)n_in; (void)out_size;
    const float* x  = (const float*)d_in[0];
    const float* wq = (const float*)d_in[1];
    const float* bq = (const float*)d_in[2];
    const float* wk = (const float*)d_in[3];
    const float* bk = (const float*)d_in[4];
    const float* wv = (const float*)d_in[5];
    const float* bv = (const float*)d_in[6];
    const float* wo = (const float*)d_in[7];
    const float* bo = (const float*)d_in[8];
    float* out = (float*)d_out;

    void *pqkv, *px, *pc, *pw, *pbias;
    cudaGetSymbolAddress(&pqkv, g_qkv);
    cudaGetSymbolAddress(&px,   g_x);
    cudaGetSymbolAddress(&pc,   g_ctx);
    cudaGetSymbolAddress(&pw,   g_w);
    cudaGetSymbolAddress(&pbias, g_bias);
    __half* qkv = (__half*)pqkv;
    __half* xh  = (__half*)px;
    __half* ctx = (__half*)pc;
    __half* wh  = (__half*)pw;
    float* biasqkv = (float*)pbias;

    cudaFuncSetAttribute(attn_mma_kernel,    cudaFuncAttributeMaxDynamicSharedMemorySize, ATTN_SMEM);
    cudaFuncSetAttribute(gemm_mma_kernel<0>, cudaFuncAttributeMaxDynamicSharedMemorySize, GEMM_SMEM);
    cudaFuncSetAttribute(gemm_mma_kernel<1>, cudaFuncAttributeMaxDynamicSharedMemorySize, GEMM_SMEM);

    // bias concat [bq; bk; bv]
    cudaMemcpyAsync(biasqkv,          bq, DD * sizeof(float), cudaMemcpyDeviceToDevice);
    cudaMemcpyAsync(biasqkv + DD,     bk, DD * sizeof(float), cudaMemcpyDeviceToDevice);
    cudaMemcpyAsync(biasqkv + 2 * DD, bv, DD * sizeof(float), cudaMemcpyDeviceToDevice);

    // fp32 -> fp16 converts
    {
        const int n4x = MM * DD / 4;
        convert_h_kernel<<<(n4x + 255) / 256, 256>>>(
            (const float4*)x, (uint32_t*)xh, n4x);
        const int n4wall = 4 * DD * DD / 4;
        convert_w_kernel<<<(n4wall + 255) / 256, 256>>>(
            (const float4*)wq, (const float4*)wk, (const float4*)wv, (const float4*)wo,
            (uint32_t*)wh);
    }

    // fused QKV projection: N = 1536
    gemm_mma_kernel<1><<<dim3(12, MM / 128), 256, GEMM_SMEM>>>(
        xh, wh, biasqkv, nullptr, qkv);

    attn_mma_kernel<<<dim3(8, HH, TT * BB), 256, ATTN_SMEM>>>(qkv, ctx);

    // output projection
    gemm_mma_kernel<0><<<dim3(4, MM / 128), 256, GEMM_SMEM>>>(
        ctx, wh + (size_t)3 * DD * DD, bo, out, nullptr);
}

// round 15
// speedup vs baseline: 2.5699x; 1.0371x over previous
#include <cuda_runtime.h>
#include <cuda_fp16.h>
#include <cstdint>

#define TT 4
#define BB 4
#define NN 1024
#define DD 512
#define HH 8
#define HDIM 64
#define MM (TT*BB*NN)   // 16384 total rows
#define EPSV 1e-6f

// ---------------- scratch (device globals: allocation-free rule) ----------------
__device__ __half g_qkv[3 * MM * DD];     // [q(pre-scaled by 1/8); k; v]
__device__ __half g_x[MM * DD];
__device__ __half g_ctx[MM * DD];
__device__ __half g_w[4 * DD * DD];       // [wq; wk; wv; wo]
__device__ float g_bias[3 * DD];          // [bq; bk; bv]

// ---------------- PTX helpers (base ISA: ldmatrix + mma.sync + cp.async) ------
__device__ __forceinline__ uint32_t smem_u32(const void* p) {
    uint32_t a;
    asm("{ .reg .u64 t; cvta.to.shared.u64 t, %1; cvt.u32.u64 %0, t; }" : "=r"(a) : "l"(p));
    return a;
}
__device__ __forceinline__ void ldsm_x4(uint32_t& r0, uint32_t& r1, uint32_t& r2, uint32_t& r3,
                                        uint32_t addr) {
    asm volatile("ldmatrix.sync.aligned.m8n8.x4.shared.b16 {%0,%1,%2,%3}, [%4];"
                 : "=r"(r0), "=r"(r1), "=r"(r2), "=r"(r3) : "r"(addr));
}
__device__ __forceinline__ void ldsm_x4_t(uint32_t& r0, uint32_t& r1, uint32_t& r2, uint32_t& r3,
                                          uint32_t addr) {
    asm volatile("ldmatrix.sync.aligned.m8n8.x4.trans.shared.b16 {%0,%1,%2,%3}, [%4];"
                 : "=r"(r0), "=r"(r1), "=r"(r2), "=r"(r3) : "r"(addr));
}
__device__ __forceinline__ void mma_f16(float& c0, float& c1, float& c2, float& c3,
                                        uint32_t a0, uint32_t a1, uint32_t a2, uint32_t a3,
                                        uint32_t b0, uint32_t b1) {
    asm volatile(
        "mma.sync.aligned.m16n8k16.row.col.f32.f16.f16.f32 "
        "{%0,%1,%2,%3}, {%4,%5,%6,%7}, {%8,%9}, {%0,%1,%2,%3};"
        : "+f"(c0), "+f"(c1), "+f"(c2), "+f"(c3)
        : "r"(a0), "r"(a1), "r"(a2), "r"(a3), "r"(b0), "r"(b1));
}
__device__ __forceinline__ void mma4(float* c, const uint32_t* a, uint32_t b0, uint32_t b1) {
    mma_f16(c[0], c[1], c[2], c[3], a[0], a[1], a[2], a[3], b0, b1);
}
__device__ __forceinline__ void cp16(uint32_t saddr, const void* g) {
    asm volatile("cp.async.cg.shared.global [%0], [%1], 16;" :: "r"(saddr), "l"(g) : "memory");
}
__device__ __forceinline__ void cp_commit() {
    asm volatile("cp.async.commit_group;" ::: "memory");
}
__device__ __forceinline__ void cp_wait0() {
    asm volatile("cp.async.wait_group 0;" ::: "memory");
}
__device__ __forceinline__ void cp_wait1() {
    asm volatile("cp.async.wait_group 1;" ::: "memory");
}
__device__ __forceinline__ void cp_wait2() {
    asm volatile("cp.async.wait_group 2;" ::: "memory");
}
__device__ __forceinline__ uint32_t pack_h2(float x, float y) {
    __half2 h = __floats2half2_rn(x, y);
    return *(uint32_t*)&h;
}

// ---------------- fp32 -> fp16 convert ----------------
__global__ __launch_bounds__(256) void convert_h_kernel(
    const float4* __restrict__ src, uint32_t* __restrict__ dst, int n4)
{
    int i = blockIdx.x * blockDim.x + threadIdx.x;
    if (i >= n4) return;
    float4 v = src[i];
    dst[2 * i]     = pack_h2(v.x, v.y);
    dst[2 * i + 1] = pack_h2(v.z, v.w);
}

// fused convert of all 4 weights
__global__ __launch_bounds__(256) void convert_w_kernel(
    const float4* __restrict__ w0, const float4* __restrict__ w1,
    const float4* __restrict__ w2, const float4* __restrict__ w3,
    uint32_t* __restrict__ dst)
{
    const int n4seg = DD * DD / 4;
    int i = blockIdx.x * blockDim.x + threadIdx.x;
    if (i >= 4 * n4seg) return;
    const int seg = i / n4seg;
    const int j   = i - seg * n4seg;
    const float4* src = (seg == 0) ? w0 : (seg == 1) ? w1 : (seg == 2) ? w2 : w3;
    float4 v = src[j];
    dst[2 * i]     = pack_h2(v.x, v.y);
    dst[2 * i + 1] = pack_h2(v.z, v.w);
}

// ---------------------------------------------------------------------------
// fp16 mma.sync GEMM, 2-stage cp.async pipeline, BK=64 per stage
// (8 iterations, one barrier each). CTA 128x128, 8 warps, warp tile 64x32.
// MODE 1 (QKV): seg-relocated fp16 out; q (seg 0) pre-scaled by 1/8.
// ---------------------------------------------------------------------------
#define TSTRIDE 144
#define TILE_B  (128 * TSTRIDE)    // 18432 (one operand, 128 rows x 128B + pad)
#define GSTAGE  (2 * TILE_B)       // 36864 (A + B)
#define GEMM_SMEM (2 * GSTAGE)     // 73728

template<int MODE>
__global__ __launch_bounds__(256, 2) void gemm_mma_kernel(
    const __half* __restrict__ A, const __half* __restrict__ B,
    const float* __restrict__ bias, float* __restrict__ C,
    __half* __restrict__ Ch)
{
    extern __shared__ __align__(128) char gsm[];
    const uint32_t sb = smem_u32(gsm);

    const int tid = threadIdx.x;
    const int wid = tid >> 5;
    const int lane = tid & 31;
    const int warp_m = wid & 1;
    const int warp_n = wid >> 1;
    const int m0 = blockIdx.y * 128;
    const int n0 = blockIdx.x * 128;   // global column (may exceed 512 in fused mode)

    const uint4* gA = (const uint4*)A;
    const uint4* gB = (const uint4*)B;

    auto issue_stage = [&](int c, int buf) {
        const uint32_t st = sb + buf * GSTAGE;
        #pragma unroll
        for (int i = 0; i < 4; i++) {
            const int idx = i * 256 + tid;      // 0..1023
            const int r  = idx >> 3;
            const int ch = idx & 7;
            const uint32_t so = (uint32_t)(r * TSTRIDE + ch * 16);
            const size_t ga = (size_t)(m0 + r) * 64 + c * 8 + ch;
            const size_t gb = (size_t)(n0 + r) * 64 + c * 8 + ch;
            cp16(st + so,          &gA[ga]);
            cp16(st + TILE_B + so, &gB[gb]);
        }
        cp_commit();
    };

    float acc[4][4][4];
    #pragma unroll
    for (int i = 0; i < 4; i++)
        #pragma unroll
        for (int j = 0; j < 4; j++)
            #pragma unroll
            for (int r = 0; r < 4; r++)
                acc[i][j][r] = 0.f;

    const uint32_t a_lrow = (uint32_t)(lane & 15);
    const uint32_t a_lcol = (uint32_t)((lane >> 4) * 16);
    const uint32_t b_lrow = (uint32_t)(((lane >> 4) & 1) * 8 + (lane & 7));
    const uint32_t b_lcol = (uint32_t)(((lane >> 3) & 1) * 16);

    issue_stage(0, 0);

    for (int c = 0; c < 8; c++) {
        cp_wait0();
        __syncthreads();                       // visibility of stage c + WAR guard
        if (c + 1 < 8) issue_stage(c + 1, (c + 1) & 1);

        const uint32_t st = sb + (c & 1) * GSTAGE;
        const uint32_t sA = st;
        const uint32_t sB = st + TILE_B;

        #pragma unroll
        for (int ks = 0; ks < 4; ks++) {
            const uint32_t kb = (uint32_t)(ks * 32);
            uint32_t bh[4][2];
            #pragma unroll
            for (int p = 0; p < 2; p++) {
                const uint32_t boff =
                    (uint32_t)(warp_n * 32 + p * 16 + b_lrow) * TSTRIDE + b_lcol + kb;
                ldsm_x4(bh[2*p][0], bh[2*p][1], bh[2*p+1][0], bh[2*p+1][1], sB + boff);
            }
            #pragma unroll
            for (int mt = 0; mt < 4; mt++) {
                const uint32_t aoff =
                    (uint32_t)(warp_m * 64 + mt * 16 + a_lrow) * TSTRIDE + a_lcol + kb;
                uint32_t a0, a1, a2, a3;
                ldsm_x4(a0, a1, a2, a3, sA + aoff);
                #pragma unroll
                for (int nt = 0; nt < 4; nt++)
                    mma_f16(acc[mt][nt][0], acc[mt][nt][1], acc[mt][nt][2], acc[mt][nt][3],
                            a0, a1, a2, a3, bh[nt][0], bh[nt][1]);
            }
        }
    }

    // epilogue (segment-relocated for fused QKV when MODE==1; q pre-scaled)
    const int seg  = n0 >> 9;
    const int nloc = n0 & 511;
    const size_t segoff = (size_t)seg * MM * DD;
    const float sc = (MODE == 1 && seg == 0) ? 0.125f : 1.0f;
    const int rbase = m0 + warp_m * 64 + (lane >> 2);
    const int cbase = nloc + warp_n * 32 + (lane & 3) * 2;
    #pragma unroll
    for (int mt = 0; mt < 4; mt++) {
        #pragma unroll
        for (int nt = 0; nt < 4; nt++) {
            const int col = cbase + nt * 8;
            const float b0 = bias[(n0 & ~511) + col];
            const float b1 = bias[(n0 & ~511) + col + 1];
            const int r0 = rbase + mt * 16;
            const float o00 = (acc[mt][nt][0] + b0) * sc, o01 = (acc[mt][nt][1] + b1) * sc;
            const float o10 = (acc[mt][nt][2] + b0) * sc, o11 = (acc[mt][nt][3] + b1) * sc;
            if (MODE == 0) {
                *(float2*)&C[(size_t)r0 * DD + col]       = make_float2(o00, o01);
                *(float2*)&C[(size_t)(r0 + 8) * DD + col] = make_float2(o10, o11);
            } else {
                *(uint32_t*)&Ch[segoff + (size_t)r0 * DD + col]       = pack_h2(o00, o01);
                *(uint32_t*)&Ch[segoff + (size_t)(r0 + 8) * DD + col] = pack_h2(o10, o11);
            }
        }
    }
}

// ---------------------------------------------------------------------------
// fp16 tensor-core fused relu-normalized attention.
// 3-stage cp.async ring; each stage holds 128 K rows + 128 V rows,
// processed as 2x64 sub-tiles (one barrier per 128 k).
// Q (pre-scaled by 1/8) stages through buffer 2, then it joins the ring.
// ---------------------------------------------------------------------------
#define ASTRIDE 144
#define STGSZ 36864            // K(128x144) + V(128x144)
#define AK_O  0
#define AV_O  18432
#define ATTN_SMEM (3 * STGSZ)  // 110592 -> 2 CTAs/SM

__global__ __launch_bounds__(256, 2) void attn_mma_kernel(
    const __half* __restrict__ qkv,
    __half* __restrict__ ctx)
{
    extern __shared__ __align__(128) char smem_[];
    const uint32_t sb = smem_u32(smem_);

    const int tid = threadIdx.x;
    const int wid = tid >> 5;
    const int lane = tid & 31;
    const int qt = blockIdx.x;      // 0..7
    const int h  = blockIdx.y;      // 0..7
    const int tb = blockIdx.z;      // 0..15
    const size_t rowbase = (size_t)tb * NN;
    const int col0 = h * HDIM;
    const int q0 = qt * 128;
    const int cq8 = col0 >> 3;

    const uint4* gq = (const uint4*)qkv;
    const uint4* gk = (const uint4*)(qkv + (size_t)MM * DD);
    const uint4* gv = (const uint4*)(qkv + (size_t)2 * MM * DD);

    auto issue_stage = [&](int kt, int buf) {
        const uint32_t st = sb + buf * STGSZ;
        #pragma unroll
        for (int i = 0; i < 4; i++) {
            const int idx = i * 256 + tid;      // 0..1023
            const int r  = idx >> 3;            // 0..127
            const int ch = idx & 7;
            const uint32_t so = (uint32_t)(r * ASTRIDE + ch * 16);
            const size_t g = (rowbase + kt * 128 + r) * 64 + cq8 + ch;
            cp16(st + AK_O + so, &gk[g]);
            cp16(st + AV_O + so, &gv[g]);
        }
        cp_commit();
    };

    // ---- Q into buffer 2 (group 0); then K/V stages 0,1 (groups 1,2) ----
    {
        const uint32_t qb = sb + 2 * STGSZ;
        #pragma unroll
        for (int i = 0; i < 4; i++) {
            const int idx = i * 256 + tid;      // 0..1023
            const int r  = idx >> 3;
            const int ch = idx & 7;
            const size_t g = (rowbase + q0 + r) * 64 + cq8 + ch;
            const uint32_t so = (uint32_t)(r * ASTRIDE + ch * 16);
            cp16(qb + so, &gq[g]);
        }
        cp_commit();
    }
    issue_stage(0, 0);
    issue_stage(1, 1);
    cp_wait2();                 // Q complete (stages 0,1 may still be in flight)
    __syncthreads();

    const uint32_t a_lrow = (uint32_t)(lane & 15);
    const uint32_t a_lcol = (uint32_t)((lane >> 4) * 16);
    const uint32_t b_lrow = (uint32_t)(((lane >> 4) & 1) * 8 + (lane & 7));
    const uint32_t b_lcol = (uint32_t)(((lane >> 3) & 1) * 16);
    const uint32_t v_lrow = (uint32_t)(lane & 15);
    const uint32_t v_lcol = (uint32_t)((lane >> 4) * 16);

    // ---- Q fragments from buffer 2 (joins ring at kt=0's issue(2)) ----
    uint32_t qf[4][4];
    #pragma unroll
    for (int ks = 0; ks < 4; ks++) {
        const uint32_t aoff = (uint32_t)(wid * 16 + a_lrow) * ASTRIDE + a_lcol + ks * 32;
        ldsm_x4(qf[ks][0], qf[ks][1], qf[ks][2], qf[ks][3], sb + 2 * STGSZ + aoff);
    }

    float acc[8][4];
    #pragma unroll
    for (int i = 0; i < 8; i++)
        #pragma unroll
        for (int j = 0; j < 4; j++)
            acc[i][j] = 0.f;
    float dsum0 = 0.f, dsum1 = 0.f;

    for (int kt = 0; kt < 8; kt++) {
        if (kt < 7) cp_wait1(); else cp_wait0();
        __syncthreads();        // stage kt visible; Q-frag reads / old readers done
        if (kt + 2 < 8) issue_stage(kt + 2, (kt + 2) % 3);

        const uint32_t st = sb + (kt % 3) * STGSZ;

        #pragma unroll
        for (int h2 = 0; h2 < 2; h2++) {
            const uint32_t rowoff = (uint32_t)(h2 * 64);

            // ---- phase 1: S = Q K^T (Q pre-scaled by 1/8) ----
            float s[8][4];
            #pragma unroll
            for (int i = 0; i < 8; i++)
                #pragma unroll
                for (int j = 0; j < 4; j++)
                    s[i][j] = 0.f;

            #pragma unroll
            for (int ks = 0; ks < 4; ks++) {
                #pragma unroll
                for (int p = 0; p < 4; p++) {
                    const uint32_t boff =
                        (rowoff + p * 16 + b_lrow) * ASTRIDE + b_lcol + ks * 32;
                    uint32_t k0, k1, k2, k3;
                    ldsm_x4(k0, k1, k2, k3, st + AK_O + boff);
                    mma4(s[2*p],     qf[ks], k0, k1);
                    mma4(s[2*p + 1], qf[ks], k2, k3);
                }
            }

            // ---- relu, denominator, repack as A fragments ----
            #pragma unroll
            for (int nt = 0; nt < 8; nt++) {
                #pragma unroll
                for (int e = 0; e < 4; e++)
                    s[nt][e] = fmaxf(s[nt][e], 0.f);
                dsum0 += s[nt][0] + s[nt][1];
                dsum1 += s[nt][2] + s[nt][3];
            }
            uint32_t af[4][4];
            #pragma unroll
            for (int g = 0; g < 4; g++) {
                af[g][0] = pack_h2(s[2*g][0],     s[2*g][1]);
                af[g][1] = pack_h2(s[2*g][2],     s[2*g][3]);
                af[g][2] = pack_h2(s[2*g + 1][0], s[2*g + 1][1]);
                af[g][3] = pack_h2(s[2*g + 1][2], s[2*g + 1][3]);
            }

            // ---- phase 2: ctx += S V (V natural + ldmatrix.trans) ----
            #pragma unroll
            for (int g = 0; g < 4; g++) {
                const uint32_t grow = (rowoff + g * 16 + v_lrow) * ASTRIDE + v_lcol;
                #pragma unroll
                for (int p = 0; p < 4; p++) {
                    const uint32_t vaddr = grow + p * 32;
                    uint32_t v0, v1, v2, v3;
                    ldsm_x4_t(v0, v1, v2, v3, st + AV_O + vaddr);
                    mma4(acc[2*p],     af[g], v0, v1);
                    mma4(acc[2*p + 1], af[g], v2, v3);
                }
            }
        }
    }

    // ---- denominator reduce across the quad (cols), normalize, write ----
    dsum0 += __shfl_xor_sync(0xffffffffu, dsum0, 1);
    dsum0 += __shfl_xor_sync(0xffffffffu, dsum0, 2);
    dsum1 += __shfl_xor_sync(0xffffffffu, dsum1, 1);
    dsum1 += __shfl_xor_sync(0xffffffffu, dsum1, 2);
    const float inv0 = 1.f / (dsum0 + EPSV);
    const float inv1 = 1.f / (dsum1 + EPSV);

    const size_t r0 = rowbase + q0 + wid * 16 + (lane >> 2);
    const int ccol = (lane & 3) * 2;
    #pragma unroll
    for (int nt = 0; nt < 8; nt++) {
        const int col = col0 + nt * 8 + ccol;
        *(uint32_t*)&ctx[r0 * DD + col]       = pack_h2(acc[nt][0] * inv0, acc[nt][1] * inv0);
        *(uint32_t*)&ctx[(r0 + 8) * DD + col] = pack_h2(acc[nt][2] * inv1, acc[nt][3] * inv1);
    }
}

// ---------------------------------------------------------------------------
extern "C" void kernel_launch(void* const* d_in, const int* in_sizes, int n_in,
                              void* d_out, int out_size)
{
    (void)in_sizes; (void)n_in; (void)out_size;
    const float* x  = (const float*)d_in[0];
    const float* wq = (const float*)d_in[1];
    const float* bq = (const float*)d_in[2];
    const float* wk = (const float*)d_in[3];
    const float* bk = (const float*)d_in[4];
    const float* wv = (const float*)d_in[5];
    const float* bv = (const float*)d_in[6];
    const float* wo = (const float*)d_in[7];
    const float* bo = (const float*)d_in[8];
    float* out = (float*)d_out;

    void *pqkv, *px, *pc, *pw, *pbias;
    cudaGetSymbolAddress(&pqkv, g_qkv);
    cudaGetSymbolAddress(&px,   g_x);
    cudaGetSymbolAddress(&pc,   g_ctx);
    cudaGetSymbolAddress(&pw,   g_w);
    cudaGetSymbolAddress(&pbias, g_bias);
    __half* qkv = (__half*)pqkv;
    __half* xh  = (__half*)px;
    __half* ctx = (__half*)pc;
    __half* wh  = (__half*)pw;
    float* biasqkv = (float*)pbias;

    cudaFuncSetAttribute(attn_mma_kernel,    cudaFuncAttributeMaxDynamicSharedMemorySize, ATTN_SMEM);
    cudaFuncSetAttribute(gemm_mma_kernel<0>, cudaFuncAttributeMaxDynamicSharedMemorySize, GEMM_SMEM);
    cudaFuncSetAttribute(gemm_mma_kernel<1>, cudaFuncAttributeMaxDynamicSharedMemorySize, GEMM_SMEM);

    // bias concat [bq; bk; bv]
    cudaMemcpyAsync(biasqkv,          bq, DD * sizeof(float), cudaMemcpyDeviceToDevice);
    cudaMemcpyAsync(biasqkv + DD,     bk, DD * sizeof(float), cudaMemcpyDeviceToDevice);
    cudaMemcpyAsync(biasqkv + 2 * DD, bv, DD * sizeof(float), cudaMemcpyDeviceToDevice);

    // fp32 -> fp16 converts
    {
        const int n4x = MM * DD / 4;
        convert_h_kernel<<<(n4x + 255) / 256, 256>>>(
            (const float4*)x, (uint32_t*)xh, n4x);
        const int n4wall = 4 * DD * DD / 4;
        convert_w_kernel<<<(n4wall + 255) / 256, 256>>>(
            (const float4*)wq, (const float4*)wk, (const float4*)wv, (const float4*)wo,
            (uint32_t*)wh);
    }

    // fused QKV projection: N = 1536 (q output pre-scaled by 1/8)
    gemm_mma_kernel<1><<<dim3(12, MM / 128), 256, GEMM_SMEM>>>(
        xh, wh, biasqkv, nullptr, qkv);

    attn_mma_kernel<<<dim3(8, HH, TT * BB), 256, ATTN_SMEM>>>(qkv, ctx);

    // output projection
    gemm_mma_kernel<0><<<dim3(4, MM / 128), 256, GEMM_SMEM>>>(
        ctx, wh + (size_t)3 * DD * DD, bo, out, nullptr);
}

// round 16
// speedup vs baseline: 2.6364x; 1.0259x over previous
#include <cuda_runtime.h>
#include <cuda_fp16.h>
#include <cstdint>

#define TT 4
#define BB 4
#define NN 1024
#define DD 512
#define HH 8
#define HDIM 64
#define MM (TT*BB*NN)   // 16384 total rows
#define EPSV 1e-6f

// ---------------- scratch (device globals: allocation-free rule) ----------------
__device__ __half g_qkv[3 * MM * DD];     // [q(pre-scaled by 1/8); k; v]
__device__ __half g_x[MM * DD];
__device__ __half g_ctx[MM * DD];
__device__ __half g_w[4 * DD * DD];       // [wq; wk; wv; wo]
__device__ float g_bias[3 * DD];          // [bq; bk; bv]

// ---------------- PTX helpers (base ISA: ldmatrix + mma.sync + cp.async) ------
__device__ __forceinline__ uint32_t smem_u32(const void* p) {
    uint32_t a;
    asm("{ .reg .u64 t; cvta.to.shared.u64 t, %1; cvt.u32.u64 %0, t; }" : "=r"(a) : "l"(p));
    return a;
}
__device__ __forceinline__ void ldsm_x4(uint32_t& r0, uint32_t& r1, uint32_t& r2, uint32_t& r3,
                                        uint32_t addr) {
    asm volatile("ldmatrix.sync.aligned.m8n8.x4.shared.b16 {%0,%1,%2,%3}, [%4];"
                 : "=r"(r0), "=r"(r1), "=r"(r2), "=r"(r3) : "r"(addr));
}
__device__ __forceinline__ void ldsm_x4_t(uint32_t& r0, uint32_t& r1, uint32_t& r2, uint32_t& r3,
                                          uint32_t addr) {
    asm volatile("ldmatrix.sync.aligned.m8n8.x4.trans.shared.b16 {%0,%1,%2,%3}, [%4];"
                 : "=r"(r0), "=r"(r1), "=r"(r2), "=r"(r3) : "r"(addr));
}
__device__ __forceinline__ void mma_f16(float& c0, float& c1, float& c2, float& c3,
                                        uint32_t a0, uint32_t a1, uint32_t a2, uint32_t a3,
                                        uint32_t b0, uint32_t b1) {
    asm volatile(
        "mma.sync.aligned.m16n8k16.row.col.f32.f16.f16.f32 "
        "{%0,%1,%2,%3}, {%4,%5,%6,%7}, {%8,%9}, {%0,%1,%2,%3};"
        : "+f"(c0), "+f"(c1), "+f"(c2), "+f"(c3)
        : "r"(a0), "r"(a1), "r"(a2), "r"(a3), "r"(b0), "r"(b1));
}
__device__ __forceinline__ void mma4(float* c, const uint32_t* a, uint32_t b0, uint32_t b1) {
    mma_f16(c[0], c[1], c[2], c[3], a[0], a[1], a[2], a[3], b0, b1);
}
__device__ __forceinline__ void cp16(uint32_t saddr, const void* g) {
    asm volatile("cp.async.cg.shared.global [%0], [%1], 16;" :: "r"(saddr), "l"(g) : "memory");
}
__device__ __forceinline__ void cp_commit() {
    asm volatile("cp.async.commit_group;" ::: "memory");
}
__device__ __forceinline__ void cp_wait0() {
    asm volatile("cp.async.wait_group 0;" ::: "memory");
}
__device__ __forceinline__ void cp_wait1() {
    asm volatile("cp.async.wait_group 1;" ::: "memory");
}
__device__ __forceinline__ void cp_wait2() {
    asm volatile("cp.async.wait_group 2;" ::: "memory");
}
__device__ __forceinline__ uint32_t pack_h2(float x, float y) {
    __half2 h = __floats2half2_rn(x, y);
    return *(uint32_t*)&h;
}

// ---------------- fp32 -> fp16 convert ----------------
__global__ __launch_bounds__(256) void convert_h_kernel(
    const float4* __restrict__ src, uint32_t* __restrict__ dst, int n4)
{
    int i = blockIdx.x * blockDim.x + threadIdx.x;
    if (i >= n4) return;
    float4 v = src[i];
    dst[2 * i]     = pack_h2(v.x, v.y);
    dst[2 * i + 1] = pack_h2(v.z, v.w);
}

// fused convert of all 4 weights
__global__ __launch_bounds__(256) void convert_w_kernel(
    const float4* __restrict__ w0, const float4* __restrict__ w1,
    const float4* __restrict__ w2, const float4* __restrict__ w3,
    uint32_t* __restrict__ dst)
{
    const int n4seg = DD * DD / 4;
    int i = blockIdx.x * blockDim.x + threadIdx.x;
    if (i >= 4 * n4seg) return;
    const int seg = i / n4seg;
    const int j   = i - seg * n4seg;
    const float4* src = (seg == 0) ? w0 : (seg == 1) ? w1 : (seg == 2) ? w2 : w3;
    float4 v = src[j];
    dst[2 * i]     = pack_h2(v.x, v.y);
    dst[2 * i + 1] = pack_h2(v.z, v.w);
}

// ---------------------------------------------------------------------------
// fp16 mma.sync GEMM, 2-stage cp.async pipeline, BK=64 per stage
// (8 iterations, one barrier each). CTA 128x128, 8 warps, warp tile 64x32.
// MODE 1 (QKV): seg-relocated fp16 out; q (seg 0) pre-scaled by 1/8.
// ---------------------------------------------------------------------------
#define TSTRIDE 144
#define TILE_B  (128 * TSTRIDE)    // 18432
#define GSTAGE  (2 * TILE_B)       // 36864 (A + B)
#define GEMM_SMEM (2 * GSTAGE)     // 73728

template<int MODE>
__global__ __launch_bounds__(256, 2) void gemm_mma_kernel(
    const __half* __restrict__ A, const __half* __restrict__ B,
    const float* __restrict__ bias, float* __restrict__ C,
    __half* __restrict__ Ch)
{
    extern __shared__ __align__(128) char gsm[];
    const uint32_t sb = smem_u32(gsm);

    const int tid = threadIdx.x;
    const int wid = tid >> 5;
    const int lane = tid & 31;
    const int warp_m = wid & 1;
    const int warp_n = wid >> 1;
    const int m0 = blockIdx.y * 128;
    const int n0 = blockIdx.x * 128;

    const uint4* gA = (const uint4*)A;
    const uint4* gB = (const uint4*)B;

    auto issue_stage = [&](int c, int buf) {
        const uint32_t st = sb + buf * GSTAGE;
        #pragma unroll
        for (int i = 0; i < 4; i++) {
            const int idx = i * 256 + tid;
            const int r  = idx >> 3;
            const int ch = idx & 7;
            const uint32_t so = (uint32_t)(r * TSTRIDE + ch * 16);
            const size_t ga = (size_t)(m0 + r) * 64 + c * 8 + ch;
            const size_t gb = (size_t)(n0 + r) * 64 + c * 8 + ch;
            cp16(st + so,          &gA[ga]);
            cp16(st + TILE_B + so, &gB[gb]);
        }
        cp_commit();
    };

    float acc[4][4][4];
    #pragma unroll
    for (int i = 0; i < 4; i++)
        #pragma unroll
        for (int j = 0; j < 4; j++)
            #pragma unroll
            for (int r = 0; r < 4; r++)
                acc[i][j][r] = 0.f;

    const uint32_t a_lrow = (uint32_t)(lane & 15);
    const uint32_t a_lcol = (uint32_t)((lane >> 4) * 16);
    const uint32_t b_lrow = (uint32_t)(((lane >> 4) & 1) * 8 + (lane & 7));
    const uint32_t b_lcol = (uint32_t)(((lane >> 3) & 1) * 16);

    issue_stage(0, 0);

    for (int c = 0; c < 8; c++) {
        cp_wait0();
        __syncthreads();
        if (c + 1 < 8) issue_stage(c + 1, (c + 1) & 1);

        const uint32_t st = sb + (c & 1) * GSTAGE;
        const uint32_t sA = st;
        const uint32_t sB = st + TILE_B;

        #pragma unroll
        for (int ks = 0; ks < 4; ks++) {
            const uint32_t kb = (uint32_t)(ks * 32);
            uint32_t bh[4][2];
            #pragma unroll
            for (int p = 0; p < 2; p++) {
                const uint32_t boff =
                    (uint32_t)(warp_n * 32 + p * 16 + b_lrow) * TSTRIDE + b_lcol + kb;
                ldsm_x4(bh[2*p][0], bh[2*p][1], bh[2*p+1][0], bh[2*p+1][1], sB + boff);
            }
            #pragma unroll
            for (int mt = 0; mt < 4; mt++) {
                const uint32_t aoff =
                    (uint32_t)(warp_m * 64 + mt * 16 + a_lrow) * TSTRIDE + a_lcol + kb;
                uint32_t a0, a1, a2, a3;
                ldsm_x4(a0, a1, a2, a3, sA + aoff);
                #pragma unroll
                for (int nt = 0; nt < 4; nt++)
                    mma_f16(acc[mt][nt][0], acc[mt][nt][1], acc[mt][nt][2], acc[mt][nt][3],
                            a0, a1, a2, a3, bh[nt][0], bh[nt][1]);
            }
        }
    }

    const int seg  = n0 >> 9;
    const int nloc = n0 & 511;
    const size_t segoff = (size_t)seg * MM * DD;
    const float sc = (MODE == 1 && seg == 0) ? 0.125f : 1.0f;
    const int rbase = m0 + warp_m * 64 + (lane >> 2);
    const int cbase = nloc + warp_n * 32 + (lane & 3) * 2;
    #pragma unroll
    for (int mt = 0; mt < 4; mt++) {
        #pragma unroll
        for (int nt = 0; nt < 4; nt++) {
            const int col = cbase + nt * 8;
            const float b0 = bias[(n0 & ~511) + col];
            const float b1 = bias[(n0 & ~511) + col + 1];
            const int r0 = rbase + mt * 16;
            const float o00 = (acc[mt][nt][0] + b0) * sc, o01 = (acc[mt][nt][1] + b1) * sc;
            const float o10 = (acc[mt][nt][2] + b0) * sc, o11 = (acc[mt][nt][3] + b1) * sc;
            if (MODE == 0) {
                *(float2*)&C[(size_t)r0 * DD + col]       = make_float2(o00, o01);
                *(float2*)&C[(size_t)(r0 + 8) * DD + col] = make_float2(o10, o11);
            } else {
                *(uint32_t*)&Ch[segoff + (size_t)r0 * DD + col]       = pack_h2(o00, o01);
                *(uint32_t*)&Ch[segoff + (size_t)(r0 + 8) * DD + col] = pack_h2(o10, o11);
            }
        }
    }
}

// ---------------------------------------------------------------------------
// fp16 attention, wide warp tile: 4 warps x 32 q-rows (CTA=128 thr).
// 3-stage cp.async ring of 64-row K/V tiles + persistent Q smem buffer.
// Halves smem bytes/mma (256 -> 128) vs the 8-warp version.
// ---------------------------------------------------------------------------
#define ASTRIDE 144
#define STG64 18432            // K(64x144) + V(64x144)
#define AK_O  0
#define AV_O  9216
#define AQ_O  (3 * STG64)      // 55296 (persistent Q: 128x144)
#define ATTN_SMEM (3 * STG64 + 18432)  // 73728 -> 2 CTAs/SM (128 thr each)

__global__ __launch_bounds__(128, 2) void attn_mma_kernel(
    const __half* __restrict__ qkv,
    __half* __restrict__ ctx)
{
    extern __shared__ __align__(128) char smem_[];
    const uint32_t sb = smem_u32(smem_);

    const int tid = threadIdx.x;
    const int wid = tid >> 5;       // 0..3, owns q rows wid*32..+31
    const int lane = tid & 31;
    const int qt = blockIdx.x;      // 0..7
    const int h  = blockIdx.y;      // 0..7
    const int tb = blockIdx.z;      // 0..15
    const size_t rowbase = (size_t)tb * NN;
    const int col0 = h * HDIM;
    const int q0 = qt * 128;
    const int cq8 = col0 >> 3;

    const uint4* gq = (const uint4*)qkv;
    const uint4* gk = (const uint4*)(qkv + (size_t)MM * DD);
    const uint4* gv = (const uint4*)(qkv + (size_t)2 * MM * DD);

    auto issue_stage = [&](int kt, int buf) {
        const uint32_t st = sb + buf * STG64;
        #pragma unroll
        for (int i = 0; i < 4; i++) {
            const int idx = i * 128 + tid;      // 0..511
            const int r  = idx >> 3;            // 0..63
            const int ch = idx & 7;
            const uint32_t so = (uint32_t)(r * ASTRIDE + ch * 16);
            const size_t g = (rowbase + kt * 64 + r) * 64 + cq8 + ch;
            cp16(st + AK_O + so, &gk[g]);
            cp16(st + AV_O + so, &gv[g]);
        }
        cp_commit();
    };

    // ---- Q into its persistent buffer (group 0); K/V stages 0,1 ----
    {
        #pragma unroll
        for (int i = 0; i < 8; i++) {
            const int idx = i * 128 + tid;      // 0..1023
            const int r  = idx >> 3;            // 0..127
            const int ch = idx & 7;
            const size_t g = (rowbase + q0 + r) * 64 + cq8 + ch;
            const uint32_t so = (uint32_t)(r * ASTRIDE + ch * 16);
            cp16(sb + AQ_O + so, &gq[g]);
        }
        cp_commit();
    }
    issue_stage(0, 0);
    issue_stage(1, 1);
    cp_wait2();                 // Q complete
    __syncthreads();

    const uint32_t a_lrow = (uint32_t)(lane & 15);
    const uint32_t a_lcol = (uint32_t)((lane >> 4) * 16);
    const uint32_t b_lrow = (uint32_t)(((lane >> 4) & 1) * 8 + (lane & 7));
    const uint32_t b_lcol = (uint32_t)(((lane >> 3) & 1) * 16);
    const uint32_t v_lrow = (uint32_t)(lane & 15);
    const uint32_t v_lcol = (uint32_t)((lane >> 4) * 16);

    // ---- Q fragments: 32 rows (2 m-tiles of 16), 4 k-steps of 16 ----
    uint32_t qf[2][4][4];
    #pragma unroll
    for (int mt = 0; mt < 2; mt++)
        #pragma unroll
        for (int ks = 0; ks < 4; ks++) {
            const uint32_t aoff =
                (uint32_t)(wid * 32 + mt * 16 + a_lrow) * ASTRIDE + a_lcol + ks * 32;
            ldsm_x4(qf[mt][ks][0], qf[mt][ks][1], qf[mt][ks][2], qf[mt][ks][3],
                    sb + AQ_O + aoff);
        }

    float acc[2][8][4];
    #pragma unroll
    for (int m = 0; m < 2; m++)
        #pragma unroll
        for (int i = 0; i < 8; i++)
            #pragma unroll
            for (int j = 0; j < 4; j++)
                acc[m][i][j] = 0.f;
    float dsum[2][2] = {{0.f, 0.f}, {0.f, 0.f}};

    for (int kt = 0; kt < 16; kt++) {
        if (kt < 15) cp_wait1(); else cp_wait0();
        __syncthreads();        // stage kt visible; prior readers of buffer done
        if (kt + 2 < 16) issue_stage(kt + 2, (kt + 2) % 3);

        const uint32_t st = sb + (kt % 3) * STG64;

        // ---- phase 1: S = Q K^T (Q pre-scaled by 1/8) ----
        float s[2][8][4];
        #pragma unroll
        for (int m = 0; m < 2; m++)
            #pragma unroll
            for (int i = 0; i < 8; i++)
                #pragma unroll
                for (int j = 0; j < 4; j++)
                    s[m][i][j] = 0.f;

        #pragma unroll
        for (int ks = 0; ks < 4; ks++) {
            #pragma unroll
            for (int p = 0; p < 4; p++) {
                const uint32_t boff =
                    (uint32_t)(p * 16 + b_lrow) * ASTRIDE + b_lcol + ks * 32;
                uint32_t k0, k1, k2, k3;
                ldsm_x4(k0, k1, k2, k3, st + AK_O + boff);
                #pragma unroll
                for (int mt = 0; mt < 2; mt++) {
                    mma4(s[mt][2*p],     qf[mt][ks], k0, k1);
                    mma4(s[mt][2*p + 1], qf[mt][ks], k2, k3);
                }
            }
        }

        // ---- relu, denominator, repack as A fragments ----
        uint32_t af[2][4][4];
        #pragma unroll
        for (int mt = 0; mt < 2; mt++) {
            #pragma unroll
            for (int nt = 0; nt < 8; nt++) {
                #pragma unroll
                for (int e = 0; e < 4; e++)
                    s[mt][nt][e] = fmaxf(s[mt][nt][e], 0.f);
                dsum[mt][0] += s[mt][nt][0] + s[mt][nt][1];
                dsum[mt][1] += s[mt][nt][2] + s[mt][nt][3];
            }
            #pragma unroll
            for (int g = 0; g < 4; g++) {
                af[mt][g][0] = pack_h2(s[mt][2*g][0],     s[mt][2*g][1]);
                af[mt][g][1] = pack_h2(s[mt][2*g][2],     s[mt][2*g][3]);
                af[mt][g][2] = pack_h2(s[mt][2*g + 1][0], s[mt][2*g + 1][1]);
                af[mt][g][3] = pack_h2(s[mt][2*g + 1][2], s[mt][2*g + 1][3]);
            }
        }

        // ---- phase 2: ctx += S V (V natural + ldmatrix.trans) ----
        #pragma unroll
        for (int g = 0; g < 4; g++) {
            const uint32_t grow = (uint32_t)(g * 16 + v_lrow) * ASTRIDE + v_lcol;
            #pragma unroll
            for (int p = 0; p < 4; p++) {
                uint32_t v0, v1, v2, v3;
                ldsm_x4_t(v0, v1, v2, v3, st + AV_O + grow + p * 32);
                #pragma unroll
                for (int mt = 0; mt < 2; mt++) {
                    mma4(acc[mt][2*p],     af[mt][g], v0, v1);
                    mma4(acc[mt][2*p + 1], af[mt][g], v2, v3);
                }
            }
        }
    }

    // ---- denominator quad-reduce, normalize, write ----
    #pragma unroll
    for (int mt = 0; mt < 2; mt++) {
        dsum[mt][0] += __shfl_xor_sync(0xffffffffu, dsum[mt][0], 1);
        dsum[mt][0] += __shfl_xor_sync(0xffffffffu, dsum[mt][0], 2);
        dsum[mt][1] += __shfl_xor_sync(0xffffffffu, dsum[mt][1], 1);
        dsum[mt][1] += __shfl_xor_sync(0xffffffffu, dsum[mt][1], 2);
        const float inv0 = 1.f / (dsum[mt][0] + EPSV);
        const float inv1 = 1.f / (dsum[mt][1] + EPSV);

        const size_t r0 = rowbase + q0 + wid * 32 + mt * 16 + (lane >> 2);
        const int ccol = (lane & 3) * 2;
        #pragma unroll
        for (int nt = 0; nt < 8; nt++) {
            const int col = col0 + nt * 8 + ccol;
            *(uint32_t*)&ctx[r0 * DD + col] =
                pack_h2(acc[mt][nt][0] * inv0, acc[mt][nt][1] * inv0);
            *(uint32_t*)&ctx[(r0 + 8) * DD + col] =
                pack_h2(acc[mt][nt][2] * inv1, acc[mt][nt][3] * inv1);
        }
    }
}

// ---------------------------------------------------------------------------
extern "C" void kernel_launch(void* const* d_in, const int* in_sizes, int n_in,
                              void* d_out, int out_size)
{
    (void)in_sizes; (void)n_in; (void)out_size;
    const float* x  = (const float*)d_in[0];
    const float* wq = (const float*)d_in[1];
    const float* bq = (const float*)d_in[2];
    const float* wk = (const float*)d_in[3];
    const float* bk = (const float*)d_in[4];
    const float* wv = (const float*)d_in[5];
    const float* bv = (const float*)d_in[6];
    const float* wo = (const float*)d_in[7];
    const float* bo = (const float*)d_in[8];
    float* out = (float*)d_out;

    void *pqkv, *px, *pc, *pw, *pbias;
    cudaGetSymbolAddress(&pqkv, g_qkv);
    cudaGetSymbolAddress(&px,   g_x);
    cudaGetSymbolAddress(&pc,   g_ctx);
    cudaGetSymbolAddress(&pw,   g_w);
    cudaGetSymbolAddress(&pbias, g_bias);
    __half* qkv = (__half*)pqkv;
    __half* xh  = (__half*)px;
    __half* ctx = (__half*)pc;
    __half* wh  = (__half*)pw;
    float* biasqkv = (float*)pbias;

    cudaFuncSetAttribute(attn_mma_kernel,    cudaFuncAttributeMaxDynamicSharedMemorySize, ATTN_SMEM);
    cudaFuncSetAttribute(gemm_mma_kernel<0>, cudaFuncAttributeMaxDynamicSharedMemorySize, GEMM_SMEM);
    cudaFuncSetAttribute(gemm_mma_kernel<1>, cudaFuncAttributeMaxDynamicSharedMemorySize, GEMM_SMEM);

    // bias concat [bq; bk; bv]
    cudaMemcpyAsync(biasqkv,          bq, DD * sizeof(float), cudaMemcpyDeviceToDevice);
    cudaMemcpyAsync(biasqkv + DD,     bk, DD * sizeof(float), cudaMemcpyDeviceToDevice);
    cudaMemcpyAsync(biasqkv + 2 * DD, bv, DD * sizeof(float), cudaMemcpyDeviceToDevice);

    // fp32 -> fp16 converts
    {
        const int n4x = MM * DD / 4;
        convert_h_kernel<<<(n4x + 255) / 256, 256>>>(
            (const float4*)x, (uint32_t*)xh, n4x);
        const int n4wall = 4 * DD * DD / 4;
        convert_w_kernel<<<(n4wall + 255) / 256, 256>>>(
            (const float4*)wq, (const float4*)wk, (const float4*)wv, (const float4*)wo,
            (uint32_t*)wh);
    }

    // fused QKV projection: N = 1536 (q output pre-scaled by 1/8)
    gemm_mma_kernel<1><<<dim3(12, MM / 128), 256, GEMM_SMEM>>>(
        xh, wh, biasqkv, nullptr, qkv);

    attn_mma_kernel<<<dim3(8, HH, TT * BB), 128, ATTN_SMEM>>>(qkv, ctx);

    // output projection
    gemm_mma_kernel<0><<<dim3(4, MM / 128), 256, GEMM_SMEM>>>(
        ctx, wh + (size_t)3 * DD * DD, bo, out, nullptr);
}